// round 1
// baseline (speedup 1.0000x reference)
#include <cuda_runtime.h>

// HMM forward: alpha_{t+1} = (alpha_t @ A) * Bo[t],  answer = sum(alpha_{T-1})
// A: (4096,4096) f32 row-major; B: (4096,128) f32; pi: (4096,) f32; obs: (1024,) int
//
// Strategy: single persistent kernel, 128 CTAs (all co-resident on 148+ SMs),
// sense-reversing grid barrier per step. Each CTA owns 32 output columns and
// streams its 512KB column strip of A from L2 every step (A is 64MB -> L2-resident).

#define N_STATES 4096
#define SEQ_T    1024
#define N_OBS    128
#define NCTA     128
#define NTHR     256
#define COLS_PER_CTA (N_STATES / NCTA)   // 32

__device__ float    g_Bo[SEQ_T * N_STATES];   // emission gathered per step (16MB)
__device__ float    g_alpha[2][N_STATES];
__device__ unsigned g_count;                  // barrier arrival counter (resets to 0 each barrier)
__device__ unsigned g_sense;                  // flips each barrier; even #barriers/launch -> restored

// ---------------------------------------------------------------------------
// Kernel 1: gather Bo[t][j] = B[j][obs[t]]. Detects int64 vs int32 obs.
// ---------------------------------------------------------------------------
__global__ void gather_Bo_kernel(const float* __restrict__ B,
                                 const int*   __restrict__ obs_raw) {
    // Detect element width: if obs is int64 (little-endian, values in [0,128)),
    // every odd dword among the first 1024 dwords is 0. Reads only 4KB (safe
    // for both widths).
    int any = 0;
    for (int k = 1 + 2 * (int)threadIdx.x; k < 1024; k += 2 * (int)blockDim.x)
        any |= obs_raw[k];
    int is32 = __syncthreads_or(any);

    int t = blockIdx.x;
    int o = is32 ? obs_raw[t] : obs_raw[2 * t];

    for (int j = threadIdx.x; j < N_STATES; j += blockDim.x)
        g_Bo[t * N_STATES + j] = B[j * N_OBS + o];
}

// ---------------------------------------------------------------------------
// Grid barrier (centralized, sense-reversing). All CTAs must be co-resident.
// ---------------------------------------------------------------------------
__device__ __forceinline__ void grid_barrier(unsigned& local_sense, unsigned nblocks) {
    __threadfence();         // publish this CTA's stores
    __syncthreads();
    if (threadIdx.x == 0) {
        unsigned s = local_sense ^ 1u;
        local_sense = s;
        if (atomicAdd(&g_count, 1u) == nblocks - 1u) {
            g_count = 0u;
            __threadfence();
            atomicExch(&g_sense, s);
        } else {
            while (*(volatile unsigned*)&g_sense != s) { }
        }
        __threadfence();     // acquire: make other CTAs' stores visible
    }
    __syncthreads();
}

// ---------------------------------------------------------------------------
// Kernel 2: persistent forward scan.
// CTA b owns columns [b*32, b*32+32). Thread layout: cg = tid&7 (float4 column
// group), rs = tid>>3 (row slot 0..31). Warp reads 4 rows x 128B contiguous.
// ---------------------------------------------------------------------------
__global__ void __launch_bounds__(NTHR, 1)
hmm_forward_kernel(const float* __restrict__ A,
                   const float* __restrict__ pi,
                   float*       __restrict__ out) {
    __shared__ float  s_alpha[N_STATES];       // 16KB: broadcast of current alpha
    __shared__ float4 s_red[32][8];            // 4KB:  cross-rowslot reduction

    const int tid  = threadIdx.x;
    const int cta  = blockIdx.x;
    const int cg   = tid & 7;                  // column group (float4) within CTA
    const int rs   = tid >> 3;                 // row slot 0..31
    const int col0 = cta * COLS_PER_CTA;

    unsigned local_sense = 0;

    // ---- alpha0 = pi * Bo[0] (this CTA's 32 columns) ----
    if (tid < COLS_PER_CTA) {
        int j = col0 + tid;
        g_alpha[0][j] = pi[j] * g_Bo[j];
    }
    grid_barrier(local_sense, gridDim.x);      // barrier #1

    // Base pointer: A viewed as float4 rows of length N/4; this thread reads
    // column-group (col0/4 + cg) at rows rs, rs+32, ...
    const float4* __restrict__ A4 =
        reinterpret_cast<const float4*>(A) + (col0 >> 2) + cg;

    int cur = 0;
    for (int t = 1; t < SEQ_T; ++t) {
        // Stage current alpha into shared memory (1024 float4 = 4 per thread)
        const float4* asrc = reinterpret_cast<const float4*>(g_alpha[cur]);
        float4*       adst = reinterpret_cast<float4*>(s_alpha);
        #pragma unroll
        for (int k = 0; k < 4; ++k)
            adst[tid + k * NTHR] = asrc[tid + k * NTHR];
        __syncthreads();

        // Partial dot products over rows rs, rs+32, ... (128 iterations)
        float4 acc = make_float4(0.f, 0.f, 0.f, 0.f);
        #pragma unroll 8
        for (int i = rs; i < N_STATES; i += 32) {
            float  a = s_alpha[i];
            float4 v = A4[i * (N_STATES / 4)];
            acc.x = fmaf(a, v.x, acc.x);
            acc.y = fmaf(a, v.y, acc.y);
            acc.z = fmaf(a, v.z, acc.z);
            acc.w = fmaf(a, v.w, acc.w);
        }

        // Reduce across 32 row slots
        s_red[rs][cg] = acc;
        __syncthreads();
        #pragma unroll
        for (int s = 16; s > 0; s >>= 1) {
            if (rs < s) {
                float4 o = s_red[rs + s][cg];
                float4 m = s_red[rs][cg];
                m.x += o.x; m.y += o.y; m.z += o.z; m.w += o.w;
                s_red[rs][cg] = m;
            }
            __syncthreads();
        }

        // Apply emission and publish new alpha (threads with rs==0, i.e. tid<8)
        if (rs == 0) {
            float4 r = s_red[0][cg];
            float4 b = reinterpret_cast<const float4*>(g_Bo + t * N_STATES)[(col0 >> 2) + cg];
            float4 o4;
            o4.x = r.x * b.x; o4.y = r.y * b.y; o4.z = r.z * b.z; o4.w = r.w * b.w;
            reinterpret_cast<float4*>(g_alpha[cur ^ 1])[(col0 >> 2) + cg] = o4;
        }

        grid_barrier(local_sense, gridDim.x);  // barriers #2..#1024 (total even)
        cur ^= 1;
    }

    // ---- final sum over alpha (CTA 0 only; last barrier made writes visible) ----
    if (cta == 0) {
        float s = 0.f;
        for (int i = tid; i < N_STATES; i += NTHR)
            s += g_alpha[cur][i];
        s_alpha[tid] = s;
        __syncthreads();
        #pragma unroll
        for (int k = NTHR / 2; k > 0; k >>= 1) {
            if (tid < k) s_alpha[tid] += s_alpha[tid + k];
            __syncthreads();
        }
        if (tid == 0) out[0] = s_alpha[0];
    }
}

// ---------------------------------------------------------------------------
extern "C" void kernel_launch(void* const* d_in, const int* in_sizes, int n_in,
                              void* d_out, int out_size) {
    const float* A   = (const float*)d_in[0];
    const float* B   = (const float*)d_in[1];
    const float* pi  = (const float*)d_in[2];
    const int*   obs = (const int*)d_in[3];   // width auto-detected in kernel
    float* out = (float*)d_out;

    gather_Bo_kernel<<<SEQ_T, 256>>>(B, obs);
    hmm_forward_kernel<<<NCTA, NTHR>>>(A, pi, out);
}

// round 3
// speedup vs baseline: 1.0593x; 1.0593x over previous
#include <cuda_runtime.h>

// HMM forward: alpha_{t+1} = (alpha_t @ A) * Bo[t],  answer = sum(alpha_{T-1})
// A: (4096,4096) f32 row-major; B: (4096,128) f32; pi: (4096,) f32; obs: (1024,) int
//
// R3 = R1's EXACT numerics (256 thr, 32 row slots, smem reduction tree — the
// accumulation order that measured rel_err 9.477e-4) + SMEM pinning of the
// first 1632 rows of each CTA's 512KB A-strip (204KB). The pinned rows are
// read in the identical order with identical fp32 FMAs, so results are
// bit-identical to R1 while L2 traffic drops 64MB -> 38.5MB per step.

#define N_STATES 4096
#define SEQ_T    1024
#define N_OBS    128
#define NCTA     128
#define NTHR     256
#define COLS_PER_CTA (N_STATES / NCTA)   // 32
#define S_ROWS   1632                    // pinned rows (multiple of 32)

// dynamic smem: pinned A strip + s_alpha(16KB) + s_red(4KB)
#define SMEM_BYTES (S_ROWS * 128 + N_STATES * 4 + 32 * 8 * 16)

__device__ float    g_Bo[SEQ_T * N_STATES];
__device__ float    g_alpha[2][N_STATES];
__device__ unsigned g_count;
__device__ unsigned g_sense;   // even number of barriers per launch -> restored

// ---------------------------------------------------------------------------
__global__ void gather_Bo_kernel(const float* __restrict__ B,
                                 const int*   __restrict__ obs_raw) {
    // int64 vs int32 detection: for int64 obs (values < 128), odd dwords are 0.
    int any = 0;
    for (int k = 1 + 2 * (int)threadIdx.x; k < 1024; k += 2 * (int)blockDim.x)
        any |= obs_raw[k];
    int is32 = __syncthreads_or(any);

    int t = blockIdx.x;
    int o = is32 ? obs_raw[t] : obs_raw[2 * t];

    for (int j = threadIdx.x; j < N_STATES; j += blockDim.x)
        g_Bo[t * N_STATES + j] = B[j * N_OBS + o];
}

// ---------------------------------------------------------------------------
__device__ __forceinline__ void grid_barrier(unsigned& local_sense, unsigned nblocks) {
    __threadfence();
    __syncthreads();
    if (threadIdx.x == 0) {
        unsigned s = local_sense ^ 1u;
        local_sense = s;
        if (atomicAdd(&g_count, 1u) == nblocks - 1u) {
            g_count = 0u;
            __threadfence();
            atomicExch(&g_sense, s);
        } else {
            while (*(volatile unsigned*)&g_sense != s) { }
        }
        __threadfence();
    }
    __syncthreads();
}

// ---------------------------------------------------------------------------
// Thread layout (IDENTICAL to R1): cg = tid&7 (float4 column group),
// rs = tid>>3 (row slot 0..31). Reduction: R1's 5-level smem tree.
// ---------------------------------------------------------------------------
__global__ void __launch_bounds__(NTHR, 1)
hmm_forward_kernel(const float* __restrict__ A,
                   const float* __restrict__ pi,
                   float*       __restrict__ out) {
    extern __shared__ float smem[];
    float4* sA      = reinterpret_cast<float4*>(smem);                 // S_ROWS*8
    float*  s_alpha = smem + S_ROWS * 32;                              // 4096
    float4 (*s_red)[8] = reinterpret_cast<float4(*)[8]>(s_alpha + N_STATES); // [32][8]

    const int tid  = threadIdx.x;
    const int cta  = blockIdx.x;
    const int cg   = tid & 7;
    const int rs   = tid >> 3;            // 0..31
    const int col0 = cta * COLS_PER_CTA;

    const float4* __restrict__ A4base = reinterpret_cast<const float4*>(A) + (col0 >> 2);
    const float4* __restrict__ A4     = A4base + cg;

    // ---- prologue: pin rows [0, S_ROWS) of this CTA's strip into SMEM ----
    for (int idx = tid; idx < S_ROWS * 8; idx += NTHR)
        sA[idx] = A4base[(idx >> 3) * (N_STATES / 4) + (idx & 7)];

    unsigned local_sense = 0;

    // ---- alpha0 = pi * Bo[0] ----
    if (tid < COLS_PER_CTA) {
        int j = col0 + tid;
        g_alpha[0][j] = pi[j] * g_Bo[j];
    }
    grid_barrier(local_sense, gridDim.x);          // barrier #1

    int cur = 0;
    for (int t = 1; t < SEQ_T; ++t) {
        // stage alpha into smem (1024 float4 = 4 per thread), as in R1
        {
            const float4* asrc = reinterpret_cast<const float4*>(g_alpha[cur]);
            float4*       adst = reinterpret_cast<float4*>(s_alpha);
            #pragma unroll
            for (int k = 0; k < 4; ++k)
                adst[tid + k * NTHR] = asrc[tid + k * NTHR];
        }
        __syncthreads();

        // Partial dot products, i = rs, rs+32, ... ascending — SAME ORDER as
        // R1. First S_ROWS rows come from SMEM (identical values), rest from L2.
        float4 acc = make_float4(0.f, 0.f, 0.f, 0.f);
        #pragma unroll 8
        for (int i = rs; i < S_ROWS; i += 32) {
            float  a = s_alpha[i];
            float4 v = sA[i * 8 + cg];
            acc.x = fmaf(a, v.x, acc.x);
            acc.y = fmaf(a, v.y, acc.y);
            acc.z = fmaf(a, v.z, acc.z);
            acc.w = fmaf(a, v.w, acc.w);
        }
        #pragma unroll 8
        for (int i = S_ROWS + rs; i < N_STATES; i += 32) {
            float  a = s_alpha[i];
            float4 v = A4[i * (N_STATES / 4)];
            acc.x = fmaf(a, v.x, acc.x);
            acc.y = fmaf(a, v.y, acc.y);
            acc.z = fmaf(a, v.z, acc.z);
            acc.w = fmaf(a, v.w, acc.w);
        }

        // R1's reduction tree across 32 row slots (order-preserving)
        s_red[rs][cg] = acc;
        __syncthreads();
        #pragma unroll
        for (int s = 16; s > 0; s >>= 1) {
            if (rs < s) {
                float4 o = s_red[rs + s][cg];
                float4 m = s_red[rs][cg];
                m.x += o.x; m.y += o.y; m.z += o.z; m.w += o.w;
                s_red[rs][cg] = m;
            }
            __syncthreads();
        }

        // emission + publish (threads rs==0, i.e. tid<8) — as in R1
        if (rs == 0) {
            float4 r = s_red[0][cg];
            float4 b = reinterpret_cast<const float4*>(g_Bo + t * N_STATES)[(col0 >> 2) + cg];
            float4 o4;
            o4.x = r.x * b.x; o4.y = r.y * b.y; o4.z = r.z * b.z; o4.w = r.w * b.w;
            reinterpret_cast<float4*>(g_alpha[cur ^ 1])[(col0 >> 2) + cg] = o4;
        }

        grid_barrier(local_sense, gridDim.x);      // barriers #2..#1024 (even total)
        cur ^= 1;
    }

    // ---- final sum (CTA 0), identical to R1 ----
    if (cta == 0) {
        float s = 0.f;
        for (int i = tid; i < N_STATES; i += NTHR)
            s += g_alpha[cur][i];
        s_alpha[tid] = s;
        __syncthreads();
        #pragma unroll
        for (int k = NTHR / 2; k > 0; k >>= 1) {
            if (tid < k) s_alpha[tid] += s_alpha[tid + k];
            __syncthreads();
        }
        if (tid == 0) out[0] = s_alpha[0];
    }
}

// ---------------------------------------------------------------------------
extern "C" void kernel_launch(void* const* d_in, const int* in_sizes, int n_in,
                              void* d_out, int out_size) {
    const float* A   = (const float*)d_in[0];
    const float* B   = (const float*)d_in[1];
    const float* pi  = (const float*)d_in[2];
    const int*   obs = (const int*)d_in[3];
    float* out = (float*)d_out;

    cudaFuncSetAttribute(hmm_forward_kernel,
                         cudaFuncAttributeMaxDynamicSharedMemorySize, SMEM_BYTES);

    gather_Bo_kernel<<<SEQ_T, 256>>>(B, obs);
    hmm_forward_kernel<<<NCTA, NTHR, SMEM_BYTES>>>(A, pi, out);
}

// round 4
// speedup vs baseline: 1.1999x; 1.1327x over previous
#include <cuda_runtime.h>

// HMM forward: alpha_{t+1} = (alpha_t @ A) * Bo[t],  answer = sum(alpha_{T-1})
//
// R4 = R3 + register-file pinning. Three-tier storage of each CTA's 512KB
// column strip of A (CTA owns 32 cols, thread owns 4 cols x row-slot rs):
//   k in [0,48)    rows [0,1536)    -> registers (48 float4/thread = 192 regs)
//   k in [48,99)   rows [1536,3168) -> SMEM (204KB pin)
//   k in [99,128)  rows [3168,4096) -> L2 (116KB/CTA/step, was 512KB in R1)
// Accumulation order (k ascending, R1's 5-level tree) is preserved exactly ->
// bit-identical results to R1/R3 (measured rel_err 9.477166e-4).

#define N_STATES 4096
#define SEQ_T    1024
#define N_OBS    128
#define NCTA     128
#define NTHR     256
#define COLS_PER_CTA (N_STATES / NCTA)   // 32

#define KR 48                    // k-slots pinned in registers
#define KS 51                    // k-slots pinned in SMEM
#define R_ROWS (KR * 32)         // 1536
#define S_ROWS (KS * 32)         // 1632
#define RS_TOT (R_ROWS + S_ROWS) // 3168

// dynamic smem: pinned A strip + s_alpha(16KB) + s_red(4KB)
#define SMEM_BYTES (S_ROWS * 128 + N_STATES * 4 + 32 * 8 * 16)

__device__ float    g_Bo[SEQ_T * N_STATES];
__device__ float    g_alpha[2][N_STATES];
__device__ unsigned g_count;
__device__ unsigned g_sense;   // even number of barriers per launch -> restored

// ---------------------------------------------------------------------------
__global__ void gather_Bo_kernel(const float* __restrict__ B,
                                 const int*   __restrict__ obs_raw) {
    // int64 vs int32 detection: for int64 obs (values < 128), odd dwords are 0.
    int any = 0;
    for (int k = 1 + 2 * (int)threadIdx.x; k < 1024; k += 2 * (int)blockDim.x)
        any |= obs_raw[k];
    int is32 = __syncthreads_or(any);

    int t = blockIdx.x;
    int o = is32 ? obs_raw[t] : obs_raw[2 * t];

    for (int j = threadIdx.x; j < N_STATES; j += blockDim.x)
        g_Bo[t * N_STATES + j] = B[j * N_OBS + o];
}

// ---------------------------------------------------------------------------
__device__ __forceinline__ void grid_barrier(unsigned& local_sense, unsigned nblocks) {
    __threadfence();
    __syncthreads();
    if (threadIdx.x == 0) {
        unsigned s = local_sense ^ 1u;
        local_sense = s;
        if (atomicAdd(&g_count, 1u) == nblocks - 1u) {
            g_count = 0u;
            __threadfence();
            atomicExch(&g_sense, s);
        } else {
            while (*(volatile unsigned*)&g_sense != s) { }
        }
        __threadfence();
    }
    __syncthreads();
}

// ---------------------------------------------------------------------------
// Thread layout (IDENTICAL to R1): cg = tid&7, rs = tid>>3 (0..31).
// ---------------------------------------------------------------------------
__global__ void __launch_bounds__(NTHR, 1)
hmm_forward_kernel(const float* __restrict__ A,
                   const float* __restrict__ pi,
                   float*       __restrict__ out) {
    extern __shared__ float smem[];
    float4* sA      = reinterpret_cast<float4*>(smem);                 // S_ROWS*8
    float*  s_alpha = smem + S_ROWS * 32;                              // 4096
    float4 (*s_red)[8] = reinterpret_cast<float4(*)[8]>(s_alpha + N_STATES); // [32][8]

    const int tid  = threadIdx.x;
    const int cta  = blockIdx.x;
    const int cg   = tid & 7;
    const int rs   = tid >> 3;            // 0..31
    const int col0 = cta * COLS_PER_CTA;

    const float4* __restrict__ A4base = reinterpret_cast<const float4*>(A) + (col0 >> 2);
    const float4* __restrict__ A4     = A4base + cg;

    // ---- prologue: pin rows [0, R_ROWS) in registers ----
    float4 rA[KR];
    #pragma unroll
    for (int k = 0; k < KR; ++k)
        rA[k] = A4[(rs + 32 * k) * (N_STATES / 4)];

    // ---- prologue: pin rows [R_ROWS, R_ROWS+S_ROWS) in SMEM ----
    for (int idx = tid; idx < S_ROWS * 8; idx += NTHR)
        sA[idx] = A4base[(R_ROWS + (idx >> 3)) * (N_STATES / 4) + (idx & 7)];

    unsigned local_sense = 0;

    // ---- alpha0 = pi * Bo[0] ----
    if (tid < COLS_PER_CTA) {
        int j = col0 + tid;
        g_alpha[0][j] = pi[j] * g_Bo[j];
    }
    grid_barrier(local_sense, gridDim.x);          // barrier #1

    int cur = 0;
    for (int t = 1; t < SEQ_T; ++t) {
        // stage alpha into smem (1024 float4 = 4 per thread)
        {
            const float4* asrc = reinterpret_cast<const float4*>(g_alpha[cur]);
            float4*       adst = reinterpret_cast<float4*>(s_alpha);
            #pragma unroll
            for (int k = 0; k < 4; ++k)
                adst[tid + k * NTHR] = asrc[tid + k * NTHR];
        }
        __syncthreads();

        // Partial dots, i = rs + 32k, k ascending 0..127 — SAME ORDER as R1.
        float4 acc = make_float4(0.f, 0.f, 0.f, 0.f);

        // tier 1: registers, k in [0, KR)
        #pragma unroll
        for (int k = 0; k < KR; ++k) {
            float a = s_alpha[rs + 32 * k];
            acc.x = fmaf(a, rA[k].x, acc.x);
            acc.y = fmaf(a, rA[k].y, acc.y);
            acc.z = fmaf(a, rA[k].z, acc.z);
            acc.w = fmaf(a, rA[k].w, acc.w);
        }
        // tier 2: SMEM, rows [R_ROWS, RS_TOT)
        #pragma unroll 8
        for (int i = R_ROWS + rs; i < RS_TOT; i += 32) {
            float  a = s_alpha[i];
            float4 v = sA[(i - R_ROWS) * 8 + cg];
            acc.x = fmaf(a, v.x, acc.x);
            acc.y = fmaf(a, v.y, acc.y);
            acc.z = fmaf(a, v.z, acc.z);
            acc.w = fmaf(a, v.w, acc.w);
        }
        // tier 3: L2, rows [RS_TOT, 4096)
        #pragma unroll 8
        for (int i = RS_TOT + rs; i < N_STATES; i += 32) {
            float  a = s_alpha[i];
            float4 v = A4[i * (N_STATES / 4)];
            acc.x = fmaf(a, v.x, acc.x);
            acc.y = fmaf(a, v.y, acc.y);
            acc.z = fmaf(a, v.z, acc.z);
            acc.w = fmaf(a, v.w, acc.w);
        }

        // R1's reduction tree across 32 row slots (order-preserving)
        s_red[rs][cg] = acc;
        __syncthreads();
        #pragma unroll
        for (int s = 16; s > 0; s >>= 1) {
            if (rs < s) {
                float4 o = s_red[rs + s][cg];
                float4 m = s_red[rs][cg];
                m.x += o.x; m.y += o.y; m.z += o.z; m.w += o.w;
                s_red[rs][cg] = m;
            }
            __syncthreads();
        }

        // emission + publish (threads rs==0, i.e. tid<8)
        if (rs == 0) {
            float4 r = s_red[0][cg];
            float4 b = reinterpret_cast<const float4*>(g_Bo + t * N_STATES)[(col0 >> 2) + cg];
            float4 o4;
            o4.x = r.x * b.x; o4.y = r.y * b.y; o4.z = r.z * b.z; o4.w = r.w * b.w;
            reinterpret_cast<float4*>(g_alpha[cur ^ 1])[(col0 >> 2) + cg] = o4;
        }

        grid_barrier(local_sense, gridDim.x);      // barriers #2..#1024 (even total)
        cur ^= 1;
    }

    // ---- final sum (CTA 0), identical to R1 ----
    if (cta == 0) {
        float s = 0.f;
        for (int i = tid; i < N_STATES; i += NTHR)
            s += g_alpha[cur][i];
        s_alpha[tid] = s;
        __syncthreads();
        #pragma unroll
        for (int k = NTHR / 2; k > 0; k >>= 1) {
            if (tid < k) s_alpha[tid] += s_alpha[tid + k];
            __syncthreads();
        }
        if (tid == 0) out[0] = s_alpha[0];
    }
}

// ---------------------------------------------------------------------------
extern "C" void kernel_launch(void* const* d_in, const int* in_sizes, int n_in,
                              void* d_out, int out_size) {
    const float* A   = (const float*)d_in[0];
    const float* B   = (const float*)d_in[1];
    const float* pi  = (const float*)d_in[2];
    const int*   obs = (const int*)d_in[3];
    float* out = (float*)d_out;

    cudaFuncSetAttribute(hmm_forward_kernel,
                         cudaFuncAttributeMaxDynamicSharedMemorySize, SMEM_BYTES);

    gather_Bo_kernel<<<SEQ_T, 256>>>(B, obs);
    hmm_forward_kernel<<<NCTA, NTHR, SMEM_BYTES>>>(A, pi, out);
}

// round 5
// speedup vs baseline: 1.4128x; 1.1774x over previous
#include <cuda_runtime.h>

// HMM forward: alpha_{t+1} = (alpha_t @ A) * Bo[t],  answer = sum(alpha_{T-1})
//
// R5: warp-per-column-group layout. CTA owns 32 cols; warp w handles float4
// column group cg=w (4 cols); lane = row-slot rs (0..31). Per output element
// the FMA chain is i = rs + 32k, k ascending 0..127 (identical to R1/R3/R4),
// and the 32-slot reduction is an xor-butterfly (16,8,4,2,1) whose lane-0
// result performs exactly the additions of R1's smem tree -> bit-identical.
// FMAs use packed fma.rn.f32x2 (per-component IEEE identical to scalar FFMA).
//
// Storage tiers of each CTA's 512KB strip:
//   rows [0,1408)    registers (44 ulonglong2/thread = 176 regs)
//   rows [1408,3040) SMEM, [cg][row] layout (204KB, padded vs bank conflicts)
//   rows [3040,4096) L2 via g_A3T (transposed copy -> coalesced for this layout)

#define N_STATES 4096
#define SEQ_T    1024
#define N_OBS    128
#define NCTA     128
#define NTHR     256
#define COLS_PER_CTA 32

#define KR 44
#define KS 51
#define KT 33                       // 44+51+33 = 128
#define R_ROWS (KR * 32)            // 1408
#define S_ROWS (KS * 32)            // 1632
#define T3_OFF (R_ROWS + S_ROWS)    // 3040
#define T3_ROWS (KT * 32)           // 1056
#define S_PITCH (S_ROWS + 1)        // pad one row: de-conflicts prologue STS

// dynamic smem: sA[8][S_PITCH] float4  +  s_alpha[4096] float
#define SMEM_BYTES (8 * S_PITCH * 16 + N_STATES * 4)

__device__ float    g_Bo[SEQ_T * N_STATES];
__device__ float4   g_A3T[1024 * T3_ROWS];     // [cg_global][row-3040]
__device__ float    g_alpha[2][N_STATES];
__device__ unsigned g_count;
__device__ unsigned g_sense;   // even #barriers per launch -> restored

// ---------------------------------------------------------------------------
__global__ void gather_Bo_kernel(const float* __restrict__ B,
                                 const int*   __restrict__ obs_raw) {
    int any = 0;
    for (int k = 1 + 2 * (int)threadIdx.x; k < 1024; k += 2 * (int)blockDim.x)
        any |= obs_raw[k];
    int is32 = __syncthreads_or(any);

    int t = blockIdx.x;
    int o = is32 ? obs_raw[t] : obs_raw[2 * t];

    for (int j = threadIdx.x; j < N_STATES; j += blockDim.x)
        g_Bo[t * N_STATES + j] = B[j * N_OBS + o];
}

// ---------------------------------------------------------------------------
// Tiled transpose of rows [3040,4096) of A into g_A3T (one-time relayout).
__global__ void transpose_A3_kernel(const float* __restrict__ A) {
    __shared__ float4 tile[32][33];
    const float4* A4 = reinterpret_cast<const float4*>(A);
    int r0 = blockIdx.x * 32;            // 33 tiles over 1056 rows
    int c0 = blockIdx.y * 32;            // 32 tiles over 1024 col-groups
    int tx = threadIdx.x & 31, ty = threadIdx.x >> 5;
    #pragma unroll
    for (int p = 0; p < 4; ++p) {
        int r = r0 + ty + 8 * p;
        tile[ty + 8 * p][tx] = A4[(size_t)(T3_OFF + r) * 1024 + (c0 + tx)];
    }
    __syncthreads();
    #pragma unroll
    for (int p = 0; p < 4; ++p) {
        int c = c0 + ty + 8 * p;
        g_A3T[(size_t)c * T3_ROWS + (r0 + tx)] = tile[tx][ty + 8 * p];
    }
}

// ---------------------------------------------------------------------------
__device__ __forceinline__ void grid_barrier(unsigned& local_sense, unsigned nblocks) {
    __syncthreads();
    if (threadIdx.x == 0) {
        unsigned s = local_sense ^ 1u;
        local_sense = s;
        __threadfence();                               // release CTA's stores
        if (atomicAdd(&g_count, 1u) == nblocks - 1u) {
            g_count = 0u;
            __threadfence();
            atomicExch(&g_sense, s);
        } else {
            while (*(volatile unsigned*)&g_sense != s) { }
        }
        __threadfence();                               // acquire
    }
    __syncthreads();
}

// packed f32x2 fma: component-wise IEEE fp32 fma (bit-identical to scalar)
__device__ __forceinline__ void fma2(unsigned long long& d,
                                     unsigned long long v,
                                     unsigned long long a) {
    asm("fma.rn.f32x2 %0, %1, %2, %0;" : "+l"(d) : "l"(v), "l"(a));
}
__device__ __forceinline__ unsigned long long pack2(float a) {
    unsigned long long r;
    asm("mov.b64 %0, {%1, %2};" : "=l"(r) : "f"(a), "f"(a));
    return r;
}

// ---------------------------------------------------------------------------
__global__ void __launch_bounds__(NTHR, 1)
hmm_forward_kernel(const float* __restrict__ A,
                   const float* __restrict__ pi,
                   float*       __restrict__ out) {
    extern __shared__ float smem[];
    float4* sA      = reinterpret_cast<float4*>(smem);        // [8][S_PITCH]
    float*  s_alpha = smem + 8 * S_PITCH * 4;                 // 4096 floats

    const int tid  = threadIdx.x;
    const int cta  = blockIdx.x;
    const int lane = tid & 31;            // row slot rs
    const int cg   = tid >> 5;            // column group (warp id), 0..7
    const int gcg  = cta * 8 + cg;        // global float4 column group
    const int col0 = cta * COLS_PER_CTA;

    const ulonglong2* __restrict__ A4u =
        reinterpret_cast<const ulonglong2*>(A);
    const float4* __restrict__ A4base =
        reinterpret_cast<const float4*>(A) + cta * 8;

    // ---- prologue: tier-1 rows in registers ----
    ulonglong2 rA[KR];
    #pragma unroll
    for (int k = 0; k < KR; ++k)
        rA[k] = A4u[(size_t)(lane + 32 * k) * 1024 + gcg];

    // ---- prologue: tier-2 rows into SMEM, [cg][row] layout ----
    for (int idx = tid; idx < S_ROWS * 8; idx += NTHR) {
        int cgf = idx & 7, rr = idx >> 3;
        sA[cgf * S_PITCH + rr] = A4base[(size_t)(R_ROWS + rr) * 1024 + cgf];
    }

    const ulonglong2* __restrict__ sAw =
        reinterpret_cast<const ulonglong2*>(sA + cg * S_PITCH);
    const ulonglong2* __restrict__ A3w =
        reinterpret_cast<const ulonglong2*>(g_A3T) + (size_t)gcg * T3_ROWS;

    unsigned local_sense = 0;

    // ---- alpha0 = pi * Bo[0] ----
    if (tid < COLS_PER_CTA) {
        int j = col0 + tid;
        g_alpha[0][j] = pi[j] * g_Bo[j];
    }
    grid_barrier(local_sense, gridDim.x);          // barrier #1

    int cur = 0;
    for (int t = 1; t < SEQ_T; ++t) {
        // prefetch emission row early (independent of alpha)
        float4 bo;
        if (lane == 0)
            bo = reinterpret_cast<const float4*>(g_Bo + t * N_STATES)[gcg];

        // stage alpha into smem (1024 float4 = 4 per thread)
        {
            const float4* asrc = reinterpret_cast<const float4*>(g_alpha[cur]);
            float4*       adst = reinterpret_cast<float4*>(s_alpha);
            #pragma unroll
            for (int k = 0; k < 4; ++k)
                adst[tid + k * NTHR] = asrc[tid + k * NTHR];
        }
        __syncthreads();

        // dot-product partials: i = lane + 32k, k ascending (order contract)
        unsigned long long acc01 = 0ull, acc23 = 0ull;   // (x,y) and (z,w)

        #pragma unroll
        for (int k = 0; k < KR; ++k) {                   // tier 1: registers
            unsigned long long aa = pack2(s_alpha[lane + 32 * k]);
            fma2(acc01, rA[k].x, aa);
            fma2(acc23, rA[k].y, aa);
        }
        #pragma unroll 8
        for (int k = 0; k < KS; ++k) {                   // tier 2: SMEM
            unsigned long long aa = pack2(s_alpha[R_ROWS + lane + 32 * k]);
            ulonglong2 v = sAw[lane + 32 * k];
            fma2(acc01, v.x, aa);
            fma2(acc23, v.y, aa);
        }
        #pragma unroll 8
        for (int k = 0; k < KT; ++k) {                   // tier 3: L2 (transposed)
            unsigned long long aa = pack2(s_alpha[T3_OFF + lane + 32 * k]);
            ulonglong2 v = A3w[lane + 32 * k];
            fma2(acc01, v.x, aa);
            fma2(acc23, v.y, aa);
        }

        // unpack and xor-butterfly over the 32 lanes (== R1's tree at lane 0)
        float4 r;
        asm("mov.b64 {%0, %1}, %2;" : "=f"(r.x), "=f"(r.y) : "l"(acc01));
        asm("mov.b64 {%0, %1}, %2;" : "=f"(r.z), "=f"(r.w) : "l"(acc23));
        #pragma unroll
        for (int m = 16; m > 0; m >>= 1) {
            r.x += __shfl_xor_sync(0xffffffffu, r.x, m);
            r.y += __shfl_xor_sync(0xffffffffu, r.y, m);
            r.z += __shfl_xor_sync(0xffffffffu, r.z, m);
            r.w += __shfl_xor_sync(0xffffffffu, r.w, m);
        }

        // emission + publish (lane 0 of each warp)
        if (lane == 0) {
            float4 o4;
            o4.x = r.x * bo.x; o4.y = r.y * bo.y;
            o4.z = r.z * bo.z; o4.w = r.w * bo.w;
            reinterpret_cast<float4*>(g_alpha[cur ^ 1])[gcg] = o4;
        }

        grid_barrier(local_sense, gridDim.x);      // barriers #2..#1024 (even)
        cur ^= 1;
    }

    // ---- final sum (CTA 0), identical to R1 ----
    if (cta == 0) {
        float s = 0.f;
        for (int i = tid; i < N_STATES; i += NTHR)
            s += g_alpha[cur][i];
        s_alpha[tid] = s;
        __syncthreads();
        #pragma unroll
        for (int k = NTHR / 2; k > 0; k >>= 1) {
            if (tid < k) s_alpha[tid] += s_alpha[tid + k];
            __syncthreads();
        }
        if (tid == 0) out[0] = s_alpha[0];
    }
}

// ---------------------------------------------------------------------------
extern "C" void kernel_launch(void* const* d_in, const int* in_sizes, int n_in,
                              void* d_out, int out_size) {
    const float* A   = (const float*)d_in[0];
    const float* B   = (const float*)d_in[1];
    const float* pi  = (const float*)d_in[2];
    const int*   obs = (const int*)d_in[3];
    float* out = (float*)d_out;

    cudaFuncSetAttribute(hmm_forward_kernel,
                         cudaFuncAttributeMaxDynamicSharedMemorySize, SMEM_BYTES);

    gather_Bo_kernel<<<SEQ_T, 256>>>(B, obs);
    dim3 tgrid(T3_ROWS / 32, 1024 / 32);
    transpose_A3_kernel<<<tgrid, 256>>>(A);
    hmm_forward_kernel<<<NCTA, NTHR, SMEM_BYTES>>>(A, pi, out);
}